// round 10
// baseline (speedup 1.0000x reference)
#include <cuda_runtime.h>

#define BB 64
#define NN 1024
#define KK 8     // 7 knn + self
#define F1 16
#define D1 64    // H1*C1 = 4*16
#define D2 128   // H2*C2 = 4*32

typedef unsigned long long ull;
typedef unsigned int u32;

// Scratch (allocation-free rule: __device__ globals)
__device__ float g_xl1[BB * NN * D1];
__device__ float g_xr1[BB * NN * D1];
__device__ float g_h1 [BB * NN * D1];
__device__ float g_xl2[BB * NN * D2];
__device__ float g_xr2[BB * NN * D2];
__device__ float g_part[BB * (NN / 8) * D2];   // attn2+pool partials (4MB)
__device__ int   g_idx[BB * NN * KK];

// Packed dual-fp32 FMA (sm_103a f32x2 pipe — ptxas never emits this from C++)
__device__ __forceinline__ ull fma2(ull a, ull b, ull c) {
    ull d;
    asm("fma.rn.f32x2 %0, %1, %2, %3;" : "=l"(d) : "l"(a), "l"(b), "l"(c));
    return d;
}
__device__ __forceinline__ ull bcast2(float v) {
    ull d;
    asm("mov.b64 %0, {%1, %1};" : "=l"(d) : "r"(__float_as_uint(v)));
    return d;
}

// ---------------------------------------------------------------------------
// KNN: one batch per blockIdx.y, 256 threads/block, 4 blocks in x cover N=1024.
// ---------------------------------------------------------------------------
__global__ void knn_kernel(const float* __restrict__ pos)
{
    __shared__ float4 sp[NN];
    int b = blockIdx.y;
    const float* p = pos + (size_t)b * NN * 3;
    for (int i = threadIdx.x; i < NN; i += blockDim.x) {
        float x = p[i * 3 + 0], y = p[i * 3 + 1], z = p[i * 3 + 2];
        sp[i] = make_float4(x, y, z, x * x + y * y + z * z);
    }
    __syncthreads();

    int n = blockIdx.x * blockDim.x + threadIdx.x;  // node 0..1023
    float4 me = sp[n];

    float bd[7];
    int   bi[7];
#pragma unroll
    for (int j = 0; j < 7; j++) { bd[j] = 3.4028235e38f; bi[j] = 0; }

#pragma unroll 2
    for (int m = 0; m < NN; m++) {
        float4 q = sp[m];
        float d = me.w + q.w - 2.f * (me.x * q.x + me.y * q.y + me.z * q.z);
        if (m != n && d < bd[6]) {
            bd[6] = d; bi[6] = m;
#pragma unroll
            for (int j = 6; j > 0; j--) {
                if (bd[j] < bd[j - 1]) {   // strict: ties keep earlier index first
                    float td = bd[j]; bd[j] = bd[j - 1]; bd[j - 1] = td;
                    int   ti = bi[j]; bi[j] = bi[j - 1]; bi[j - 1] = ti;
                }
            }
        }
    }

    int* o = g_idx + ((size_t)((b << 10) + n)) * KK;
#pragma unroll
    for (int j = 0; j < 7; j++) o[j] = bi[j];
    o[7] = n;  // self loop appended last, like the reference
}

// ---------------------------------------------------------------------------
// Register-blocked GEMM (exact R7 inner body), multi-tile: out = x @ W + b.
// Each block stages W ONCE (chunk-permuted) then processes TILES tiles of
// 128 rows. 256 threads = 16(tx: cols) x 16(ty: rows); thread tile 8 rows x
// CT cols, col-pair packed f32x2 accumulators.
// Per k: 2 broadcast LDS.128 (x) + lane-dup mov.b64 (ALU pipe) + CPT W
// LDS.128 reading 256B contiguous across lanes (2 wavefronts each).
// Grid = BB*NN/(128*TILES) = 256 blocks -> single wave at 2 CTA/SM.
// ---------------------------------------------------------------------------
template<int FIN, int DOUT, int TILES>
__global__ void __launch_bounds__(256, 2) gemm_kernel(
    const float* __restrict__ x,
    const float* __restrict__ W, const float* __restrict__ bias,
    float* __restrict__ out)
{
    constexpr int CT  = DOUT / 16;           // cols per thread: 4 or 8
    constexpr int CU  = CT / 2;              // packed accumulators: 2 or 4
    constexpr int CPT = (CT / 4 > 0) ? CT / 4 : 1;  // W chunks per thread: 1 or 2
    constexpr int RXf = 132;                 // xs row stride (floats): 128 + 4

    __shared__ float xs[FIN * RXf];
    __shared__ float ws[FIN * DOUT];
    __shared__ float sb[DOUT];

    int tid   = threadIdx.x;
    int tile0 = blockIdx.x * (128 * TILES);

    // Stage W chunk-permuted once: element (k,c): chunk q=c>>2 ->
    // phys (q%CPT)*16 + q/CPT, so each W LDS.128 is contiguous across lanes.
    for (int i = tid; i < FIN * DOUT; i += 256) {
        int k = i / DOUT, c = i - k * DOUT;
        int q = c >> 2;
        int phys = (q % CPT) * 16 + (q / CPT);
        ws[k * DOUT + phys * 4 + (c & 3)] = W[i];
    }
    if (tid < DOUT) sb[tid] = bias[tid];

    int tx = tid & 15, ty = tid >> 4;
    int r0 = ty * 8, c0 = tx * CT;

#pragma unroll 1
    for (int t = 0; t < TILES; t++) {
        int base = tile0 + t * 128;

        __syncthreads();  // ws ready (t=0) / xs safe to overwrite (t>0)
        for (int i = tid; i < 128 * FIN; i += 256) {
            int r = i / FIN, k = i - r * FIN;
            xs[k * RXf + r] = x[(size_t)(base + r) * FIN + k];
        }
        __syncthreads();

        ull acc[8][CU];
        {
            const ull* bp = (const ull*)(sb + c0);
#pragma unroll
            for (int r = 0; r < 8; r++)
#pragma unroll
                for (int c = 0; c < CU; c++) acc[r][c] = bp[c];
        }

#pragma unroll 4
        for (int k = 0; k < FIN; k++) {
            const float4* xp = (const float4*)(xs + k * RXf + r0);
            float4 xa = xp[0], xb = xp[1];
            ull xv[8];
            xv[0] = bcast2(xa.x); xv[1] = bcast2(xa.y);
            xv[2] = bcast2(xa.z); xv[3] = bcast2(xa.w);
            xv[4] = bcast2(xb.x); xv[5] = bcast2(xb.y);
            xv[6] = bcast2(xb.z); xv[7] = bcast2(xb.w);

            ull wv[CU];
#pragma unroll
            for (int j = 0; j < CPT; j++) {
                ulonglong2 t2 = *(const ulonglong2*)(ws + k * DOUT + (j * 16 + tx) * 4);
                wv[2 * j] = t2.x; wv[2 * j + 1] = t2.y;
            }
#pragma unroll
            for (int r = 0; r < 8; r++)
#pragma unroll
                for (int c = 0; c < CU; c++)
                    acc[r][c] = fma2(xv[r], wv[c], acc[r][c]);
        }

#pragma unroll
        for (int r = 0; r < 8; r++) {
            ulonglong2* op = (ulonglong2*)(out + (size_t)(base + r0 + r) * DOUT + c0);
#pragma unroll
            for (int c = 0; c < CU / 2; c++)
                op[c] = make_ulonglong2(acc[r][2 * c], acc[r][2 * c + 1]);
        }
    }
}

// ---------------------------------------------------------------------------
// GATv2 attention + aggregation for layer 1, one warp per node.
// ---------------------------------------------------------------------------
__global__ void attn1_kernel(const float* __restrict__ xl, const float* __restrict__ xr,
                             const float* __restrict__ att, const float* __restrict__ bias,
                             float* __restrict__ out)
{
    constexpr int DOUT = D1, V = 2;
    int node = (blockIdx.x * blockDim.x + threadIdx.x) >> 5;
    int lane = threadIdx.x & 31;
    int b = node >> 10;
    const int* nidx = g_idx + (size_t)node * KK;
    int4 i0 = *(const int4*)nidx;
    int4 i1 = *(const int4*)(nidx + 4);
    int srcs[KK] = {i0.x, i0.y, i0.z, i0.w, i1.x, i1.y, i1.z, i1.w};

    int c0 = lane * V;

    float2 tr = *(const float2*)(xr + (size_t)node * DOUT + c0);
    float xrv[V] = {tr.x, tr.y};
    float2 ta = *(const float2*)(att + c0);
    float attv[V] = {ta.x, ta.y};

    float xnb[KK][V];
    float lg[KK];
#pragma unroll
    for (int k = 0; k < KK; k++) {
        int src = (b << 10) + srcs[k];
        float2 t = *(const float2*)(xl + (size_t)src * DOUT + c0);
        xnb[k][0] = t.x; xnb[k][1] = t.y;
        float s = 0.f;
#pragma unroll
        for (int v = 0; v < V; v++) {
            float e = xnb[k][v] + xrv[v];
            e = e > 0.f ? e : 0.2f * e;       // leaky_relu(0.2)
            s = fmaf(e, attv[v], s);
        }
        s += __shfl_xor_sync(0xffffffffu, s, 1);
        s += __shfl_xor_sync(0xffffffffu, s, 2);
        s += __shfl_xor_sync(0xffffffffu, s, 4);
        lg[k] = s;
    }

    float mx = lg[0];
#pragma unroll
    for (int k = 1; k < KK; k++) mx = fmaxf(mx, lg[k]);
    float ssum = 0.f;
#pragma unroll
    for (int k = 0; k < KK; k++) { lg[k] = __expf(lg[k] - mx); ssum += lg[k]; }
    float inv = 1.f / ssum;

    float o[V] = {0.f, 0.f};
#pragma unroll
    for (int k = 0; k < KK; k++) {
        float a = lg[k] * inv;
#pragma unroll
        for (int v = 0; v < V; v++) o[v] = fmaf(a, xnb[k][v], o[v]);
    }

    float2 bv = *(const float2*)(bias + c0);
    float2 r;
    r.x = fmaxf(o[0] + bv.x, 0.f);
    r.y = fmaxf(o[1] + bv.y, 0.f);
    *(float2*)(out + (size_t)node * DOUT + c0) = r;
}

// ---------------------------------------------------------------------------
// Layer-2 attention FUSED with partial mean-pool. 8 warps = 8 nodes per block
// (all in one batch); block partial (128 floats) to g_part.
// ---------------------------------------------------------------------------
__global__ void __launch_bounds__(256) attn2_pool_kernel(
    const float* __restrict__ xl, const float* __restrict__ xr,
    const float* __restrict__ att, const float* __restrict__ bias,
    float* __restrict__ part)
{
    constexpr int DOUT = D2, V = 4;
    __shared__ float sacc[8 * D2];

    int warp = threadIdx.x >> 5;
    int lane = threadIdx.x & 31;
    int node = blockIdx.x * 8 + warp;
    int b = node >> 10;
    const int* nidx = g_idx + (size_t)node * KK;
    int4 i0 = *(const int4*)nidx;
    int4 i1 = *(const int4*)(nidx + 4);
    int srcs[KK] = {i0.x, i0.y, i0.z, i0.w, i1.x, i1.y, i1.z, i1.w};

    int c0 = lane * V;

    float4 tr = *(const float4*)(xr + (size_t)node * DOUT + c0);
    float xrv[V] = {tr.x, tr.y, tr.z, tr.w};
    float4 ta = *(const float4*)(att + c0);
    float attv[V] = {ta.x, ta.y, ta.z, ta.w};

    float xnb[KK][V];
    float lg[KK];
#pragma unroll
    for (int k = 0; k < KK; k++) {
        int src = (b << 10) + srcs[k];
        float4 t = *(const float4*)(xl + (size_t)src * DOUT + c0);
        xnb[k][0] = t.x; xnb[k][1] = t.y; xnb[k][2] = t.z; xnb[k][3] = t.w;
        float s = 0.f;
#pragma unroll
        for (int v = 0; v < V; v++) {
            float e = xnb[k][v] + xrv[v];
            e = e > 0.f ? e : 0.2f * e;       // leaky_relu(0.2)
            s = fmaf(e, attv[v], s);
        }
        s += __shfl_xor_sync(0xffffffffu, s, 1);
        s += __shfl_xor_sync(0xffffffffu, s, 2);
        s += __shfl_xor_sync(0xffffffffu, s, 4);
        lg[k] = s;
    }

    float mx = lg[0];
#pragma unroll
    for (int k = 1; k < KK; k++) mx = fmaxf(mx, lg[k]);
    float ssum = 0.f;
#pragma unroll
    for (int k = 0; k < KK; k++) { lg[k] = __expf(lg[k] - mx); ssum += lg[k]; }
    float inv = 1.f / ssum;

    float o[V] = {0.f, 0.f, 0.f, 0.f};
#pragma unroll
    for (int k = 0; k < KK; k++) {
        float a = lg[k] * inv;
#pragma unroll
        for (int v = 0; v < V; v++) o[v] = fmaf(a, xnb[k][v], o[v]);
    }

    float4 bv = *(const float4*)(bias + c0);
    float4 r;
    r.x = fmaxf(o[0] + bv.x, 0.f);
    r.y = fmaxf(o[1] + bv.y, 0.f);
    r.z = fmaxf(o[2] + bv.z, 0.f);
    r.w = fmaxf(o[3] + bv.w, 0.f);
    *(float4*)(sacc + warp * D2 + c0) = r;
    __syncthreads();

    int t = threadIdx.x;
    if (t < D2) {
        float s = 0.f;
#pragma unroll
        for (int w = 0; w < 8; w++) s += sacc[w * D2 + t];
        part[(size_t)blockIdx.x * D2 + t] = s;
    }
}

// ---------------------------------------------------------------------------
// Final pool reduce: out[b][c] = (1/N) * sum over 128 block-partials.
// ---------------------------------------------------------------------------
__global__ void pool_reduce_kernel(const float* __restrict__ part,
                                   float* __restrict__ out)
{
    int b = blockIdx.x, t = threadIdx.x;  // 128 threads
    const float* p = part + (size_t)b * (NN / 8) * D2 + t;
    float s = 0.f;
#pragma unroll 8
    for (int j = 0; j < NN / 8; j++) s += p[(size_t)j * D2];
    out[b * D2 + t] = s * (1.f / (float)NN);
}

// ---------------------------------------------------------------------------
extern "C" void kernel_launch(void* const* d_in, const int* in_sizes, int n_in,
                              void* d_out, int out_size)
{
    const float* x     = (const float*)d_in[0];
    const float* pos   = (const float*)d_in[1];
    const float* Wl1   = (const float*)d_in[2];
    const float* bl1   = (const float*)d_in[3];
    const float* Wr1   = (const float*)d_in[4];
    const float* br1   = (const float*)d_in[5];
    const float* att1  = (const float*)d_in[6];
    const float* bias1 = (const float*)d_in[7];
    const float* Wl2   = (const float*)d_in[8];
    const float* bl2   = (const float*)d_in[9];
    const float* Wr2   = (const float*)d_in[10];
    const float* br2   = (const float*)d_in[11];
    const float* att2  = (const float*)d_in[12];
    const float* bias2 = (const float*)d_in[13];
    float* out = (float*)d_out;

    float *xl1, *xr1, *h1, *xl2, *xr2, *part;
    cudaGetSymbolAddress((void**)&xl1,  g_xl1);
    cudaGetSymbolAddress((void**)&xr1,  g_xr1);
    cudaGetSymbolAddress((void**)&h1,   g_h1);
    cudaGetSymbolAddress((void**)&xl2,  g_xl2);
    cudaGetSymbolAddress((void**)&xr2,  g_xr2);
    cudaGetSymbolAddress((void**)&part, g_part);

    const int GB = BB * NN / 256;  // 256 blocks (TILES=2, 128-row tiles)

    // Launch order chosen so the profiled launch (index 3) is attn1.
    // idx0,1: layer-1 transforms (xl1, xr1)
    gemm_kernel<F1, D1, 2><<<GB, 256>>>(x, Wl1, bl1, xl1);
    gemm_kernel<F1, D1, 2><<<GB, 256>>>(x, Wr1, br1, xr1);
    // idx2: KNN graph
    knn_kernel<<<dim3(NN / 256, BB), 256>>>(pos);
    // idx3: layer-1 attention (PROFILED)
    attn1_kernel<<<(BB * NN * 32) / 256, 256>>>(xl1, xr1, att1, bias1, h1);
    // idx4,5: layer-2 transforms
    gemm_kernel<D1, D2, 2><<<GB, 256>>>(h1, Wl2, bl2, xl2);
    gemm_kernel<D1, D2, 2><<<GB, 256>>>(h1, Wr2, br2, xr2);
    // idx6: layer-2 attention + partial mean pool
    attn2_pool_kernel<<<BB * NN / 8, 256>>>(xl2, xr2, att2, bias2, part);
    // idx7: final pool reduction
    pool_reduce_kernel<<<BB, 128>>>(part, out);
}

// round 11
// speedup vs baseline: 1.0461x; 1.0461x over previous
#include <cuda_runtime.h>

#define BB 64
#define NN 1024
#define KK 8     // 7 knn + self
#define F1 16
#define D1 64    // H1*C1 = 4*16
#define D2 128   // H2*C2 = 4*32

typedef unsigned long long ull;
typedef unsigned int u32;

// Scratch (allocation-free rule: __device__ globals)
__device__ float g_xl1[BB * NN * D1];
__device__ float g_xr1[BB * NN * D1];
__device__ float g_h1 [BB * NN * D1];
__device__ float g_xl2[BB * NN * D2];
__device__ float g_xr2[BB * NN * D2];
__device__ float g_part[BB * (NN / 8) * D2];   // attn2+pool partials (4MB)
__device__ int   g_idx[BB * NN * KK];

// Packed dual-fp32 ops (sm_103a f32x2 pipe — ptxas never emits from C++)
__device__ __forceinline__ ull fma2(ull a, ull b, ull c) {
    ull d;
    asm("fma.rn.f32x2 %0, %1, %2, %3;" : "=l"(d) : "l"(a), "l"(b), "l"(c));
    return d;
}
__device__ __forceinline__ ull add2(ull a, ull b) {
    ull d;
    asm("add.rn.f32x2 %0, %1, %2;" : "=l"(d) : "l"(a), "l"(b));
    return d;
}
__device__ __forceinline__ ull bcast2(float v) {
    ull d;
    asm("mov.b64 %0, {%1, %1};" : "=l"(d) : "r"(__float_as_uint(v)));
    return d;
}
__device__ __forceinline__ float lo32(ull v) { return __uint_as_float((u32)v); }
__device__ __forceinline__ float hi32(ull v) { return __uint_as_float((u32)(v >> 32)); }

// ---------------------------------------------------------------------------
// KNN, pair-processed: one batch per blockIdx.y, 4 x-blocks of 256 threads.
// smem in pair-interleaved SoA (per pair: x0 x1 y0 y1 z0 z1 w0 w1), so each
// iteration computes TWO candidate distances with 2x LDS.128 + 1 add2 +
// 3 fma2 (d = -2x*qx -2y*qy -2z*qz + (qw + mew)), one branch guards both
// inserts. Insert bubble is strict-< (stable, matches lax.top_k ties).
// ---------------------------------------------------------------------------
__global__ void knn_kernel(const float* __restrict__ pos)
{
    __shared__ float spp[NN * 4];   // 512 pairs x 8 floats = 16KB
    int b = blockIdx.y;
    const float* p = pos + (size_t)b * NN * 3;
    for (int i = threadIdx.x; i < NN; i += blockDim.x) {
        float x = p[i * 3 + 0], y = p[i * 3 + 1], z = p[i * 3 + 2];
        float w = x * x + y * y + z * z;
        float* q = spp + (i >> 1) * 8 + (i & 1);
        q[0] = x; q[2] = y; q[4] = z; q[6] = w;
    }
    __syncthreads();

    int n = blockIdx.x * blockDim.x + threadIdx.x;  // node 0..1023
    const float* meq = spp + (n >> 1) * 8 + (n & 1);
    float mex = meq[0], mey = meq[2], mez = meq[4], mew = meq[6];
    ull cx = bcast2(-2.f * mex), cy = bcast2(-2.f * mey),
        cz = bcast2(-2.f * mez), cw = bcast2(mew);

    float bd[7];
    int   bi[7];
#pragma unroll
    for (int j = 0; j < 7; j++) { bd[j] = 3.4028235e38f; bi[j] = 0; }

    const ulonglong2* pp = (const ulonglong2*)spp;
#pragma unroll 1
    for (int i = 0; i < NN / 2; i++) {
        ulonglong2 a  = pp[2 * i];      // {x0x1, y0y1}
        ulonglong2 c2 = pp[2 * i + 1];  // {z0z1, w0w1}
        ull d2 = add2(c2.y, cw);
        d2 = fma2(cx, a.x, d2);
        d2 = fma2(cy, a.y, d2);
        d2 = fma2(cz, c2.x, d2);
        float d0 = lo32(d2), d1 = hi32(d2);
        if (d0 < bd[6] || d1 < bd[6]) {
            int m0 = 2 * i;
            if (d0 < bd[6] && m0 != n) {
                bd[6] = d0; bi[6] = m0;
#pragma unroll
                for (int j = 6; j > 0; j--) {
                    if (bd[j] < bd[j - 1]) {   // strict: ties keep earlier index
                        float td = bd[j]; bd[j] = bd[j - 1]; bd[j - 1] = td;
                        int   ti = bi[j]; bi[j] = bi[j - 1]; bi[j - 1] = ti;
                    }
                }
            }
            if (d1 < bd[6] && (m0 + 1) != n) {
                bd[6] = d1; bi[6] = m0 + 1;
#pragma unroll
                for (int j = 6; j > 0; j--) {
                    if (bd[j] < bd[j - 1]) {
                        float td = bd[j]; bd[j] = bd[j - 1]; bd[j - 1] = td;
                        int   ti = bi[j]; bi[j] = bi[j - 1]; bi[j - 1] = ti;
                    }
                }
            }
        }
    }

    int* o = g_idx + ((size_t)((b << 10) + n)) * KK;
#pragma unroll
    for (int j = 0; j < 7; j++) o[j] = bi[j];
    o[7] = n;  // self loop appended last, like the reference
}

// ---------------------------------------------------------------------------
// Register-blocked GEMM (exact R7 body), combined Wl/Wr via grid.y.
// Block tile 128 rows x DOUT, 256 threads = 16(tx) x 16(ty); thread tile
// 8 rows x CT cols, col-pair packed f32x2 accumulators. W chunk-permuted.
// ---------------------------------------------------------------------------
template<int FIN, int DOUT>
__global__ void __launch_bounds__(256) gemm2_kernel(
    const float* __restrict__ x,
    const float* __restrict__ Wa, const float* __restrict__ ba,
    const float* __restrict__ Wb, const float* __restrict__ bb,
    float* __restrict__ outa, float* __restrict__ outb)
{
    constexpr int CT  = DOUT / 16;
    constexpr int CU  = CT / 2;
    constexpr int CPT = (CT / 4 > 0) ? CT / 4 : 1;
    constexpr int RXf = 132;

    __shared__ float xs[FIN * RXf];
    __shared__ float ws[FIN * DOUT];
    __shared__ float sb[DOUT];

    const float* W    = blockIdx.y ? Wb   : Wa;
    const float* bias = blockIdx.y ? bb   : ba;
    float*       out  = blockIdx.y ? outb : outa;

    int tid  = threadIdx.x;
    int base = blockIdx.x * 128;

    for (int i = tid; i < FIN * DOUT; i += 256) {
        int k = i / DOUT, c = i - k * DOUT;
        int q = c >> 2;
        int phys = (q % CPT) * 16 + (q / CPT);
        ws[k * DOUT + phys * 4 + (c & 3)] = W[i];
    }
    if (tid < DOUT) sb[tid] = bias[tid];
    for (int i = tid; i < 128 * FIN; i += 256) {
        int r = i / FIN, k = i - r * FIN;
        xs[k * RXf + r] = x[(size_t)(base + r) * FIN + k];
    }
    __syncthreads();

    int tx = tid & 15, ty = tid >> 4;
    int r0 = ty * 8, c0 = tx * CT;

    ull acc[8][CU];
    {
        const ull* bp = (const ull*)(sb + c0);
#pragma unroll
        for (int r = 0; r < 8; r++)
#pragma unroll
            for (int c = 0; c < CU; c++) acc[r][c] = bp[c];
    }

#pragma unroll 4
    for (int k = 0; k < FIN; k++) {
        const float4* xp = (const float4*)(xs + k * RXf + r0);
        float4 xa = xp[0], xb = xp[1];
        ull xv[8];
        xv[0] = bcast2(xa.x); xv[1] = bcast2(xa.y);
        xv[2] = bcast2(xa.z); xv[3] = bcast2(xa.w);
        xv[4] = bcast2(xb.x); xv[5] = bcast2(xb.y);
        xv[6] = bcast2(xb.z); xv[7] = bcast2(xb.w);

        ull wv[CU];
#pragma unroll
        for (int j = 0; j < CPT; j++) {
            ulonglong2 t = *(const ulonglong2*)(ws + k * DOUT + (j * 16 + tx) * 4);
            wv[2 * j] = t.x; wv[2 * j + 1] = t.y;
        }
#pragma unroll
        for (int r = 0; r < 8; r++)
#pragma unroll
            for (int c = 0; c < CU; c++)
                acc[r][c] = fma2(xv[r], wv[c], acc[r][c]);
    }

#pragma unroll
    for (int r = 0; r < 8; r++) {
        ulonglong2* op = (ulonglong2*)(out + (size_t)(base + r0 + r) * DOUT + c0);
#pragma unroll
        for (int c = 0; c < CU / 2; c++)
            op[c] = make_ulonglong2(acc[r][2 * c], acc[r][2 * c + 1]);
    }
}

// Single-matrix variant with row base (used for layer-1, 3 launches so knn
// lands at profile index 3). Same body.
template<int FIN, int DOUT>
__global__ void __launch_bounds__(256) gemm1_kernel(
    const float* __restrict__ x,
    const float* __restrict__ W, const float* __restrict__ bias,
    float* __restrict__ out, int rowbase)
{
    constexpr int CT  = DOUT / 16;
    constexpr int CU  = CT / 2;
    constexpr int CPT = (CT / 4 > 0) ? CT / 4 : 1;
    constexpr int RXf = 132;

    __shared__ float xs[FIN * RXf];
    __shared__ float ws[FIN * DOUT];
    __shared__ float sb[DOUT];

    int tid  = threadIdx.x;
    int base = rowbase + blockIdx.x * 128;

    for (int i = tid; i < FIN * DOUT; i += 256) {
        int k = i / DOUT, c = i - k * DOUT;
        int q = c >> 2;
        int phys = (q % CPT) * 16 + (q / CPT);
        ws[k * DOUT + phys * 4 + (c & 3)] = W[i];
    }
    if (tid < DOUT) sb[tid] = bias[tid];
    for (int i = tid; i < 128 * FIN; i += 256) {
        int r = i / FIN, k = i - r * FIN;
        xs[k * RXf + r] = x[(size_t)(base + r) * FIN + k];
    }
    __syncthreads();

    int tx = tid & 15, ty = tid >> 4;
    int r0 = ty * 8, c0 = tx * CT;

    ull acc[8][CU];
    {
        const ull* bp = (const ull*)(sb + c0);
#pragma unroll
        for (int r = 0; r < 8; r++)
#pragma unroll
            for (int c = 0; c < CU; c++) acc[r][c] = bp[c];
    }

#pragma unroll 4
    for (int k = 0; k < FIN; k++) {
        const float4* xp = (const float4*)(xs + k * RXf + r0);
        float4 xa = xp[0], xb = xp[1];
        ull xv[8];
        xv[0] = bcast2(xa.x); xv[1] = bcast2(xa.y);
        xv[2] = bcast2(xa.z); xv[3] = bcast2(xa.w);
        xv[4] = bcast2(xb.x); xv[5] = bcast2(xb.y);
        xv[6] = bcast2(xb.z); xv[7] = bcast2(xb.w);

        ull wv[CU];
#pragma unroll
        for (int j = 0; j < CPT; j++) {
            ulonglong2 t = *(const ulonglong2*)(ws + k * DOUT + (j * 16 + tx) * 4);
            wv[2 * j] = t.x; wv[2 * j + 1] = t.y;
        }
#pragma unroll
        for (int r = 0; r < 8; r++)
#pragma unroll
            for (int c = 0; c < CU; c++)
                acc[r][c] = fma2(xv[r], wv[c], acc[r][c]);
    }

#pragma unroll
    for (int r = 0; r < 8; r++) {
        ulonglong2* op = (ulonglong2*)(out + (size_t)(base + r0 + r) * DOUT + c0);
#pragma unroll
        for (int c = 0; c < CU / 2; c++)
            op[c] = make_ulonglong2(acc[r][2 * c], acc[r][2 * c + 1]);
    }
}

// ---------------------------------------------------------------------------
// GATv2 attention + aggregation for layer 1, one warp per node.
// ---------------------------------------------------------------------------
__global__ void attn1_kernel(const float* __restrict__ xl, const float* __restrict__ xr,
                             const float* __restrict__ att, const float* __restrict__ bias,
                             float* __restrict__ out)
{
    constexpr int DOUT = D1, V = 2;
    int node = (blockIdx.x * blockDim.x + threadIdx.x) >> 5;
    int lane = threadIdx.x & 31;
    int b = node >> 10;
    const int* nidx = g_idx + (size_t)node * KK;
    int4 i0 = *(const int4*)nidx;
    int4 i1 = *(const int4*)(nidx + 4);
    int srcs[KK] = {i0.x, i0.y, i0.z, i0.w, i1.x, i1.y, i1.z, i1.w};

    int c0 = lane * V;

    float2 tr = *(const float2*)(xr + (size_t)node * DOUT + c0);
    float xrv[V] = {tr.x, tr.y};
    float2 ta = *(const float2*)(att + c0);
    float attv[V] = {ta.x, ta.y};

    float xnb[KK][V];
    float lg[KK];
#pragma unroll
    for (int k = 0; k < KK; k++) {
        int src = (b << 10) + srcs[k];
        float2 t = *(const float2*)(xl + (size_t)src * DOUT + c0);
        xnb[k][0] = t.x; xnb[k][1] = t.y;
        float s = 0.f;
#pragma unroll
        for (int v = 0; v < V; v++) {
            float e = xnb[k][v] + xrv[v];
            e = e > 0.f ? e : 0.2f * e;       // leaky_relu(0.2)
            s = fmaf(e, attv[v], s);
        }
        s += __shfl_xor_sync(0xffffffffu, s, 1);
        s += __shfl_xor_sync(0xffffffffu, s, 2);
        s += __shfl_xor_sync(0xffffffffu, s, 4);
        lg[k] = s;
    }

    float mx = lg[0];
#pragma unroll
    for (int k = 1; k < KK; k++) mx = fmaxf(mx, lg[k]);
    float ssum = 0.f;
#pragma unroll
    for (int k = 0; k < KK; k++) { lg[k] = __expf(lg[k] - mx); ssum += lg[k]; }
    float inv = 1.f / ssum;

    float o[V] = {0.f, 0.f};
#pragma unroll
    for (int k = 0; k < KK; k++) {
        float a = lg[k] * inv;
#pragma unroll
        for (int v = 0; v < V; v++) o[v] = fmaf(a, xnb[k][v], o[v]);
    }

    float2 bv = *(const float2*)(bias + c0);
    float2 r;
    r.x = fmaxf(o[0] + bv.x, 0.f);
    r.y = fmaxf(o[1] + bv.y, 0.f);
    *(float2*)(out + (size_t)node * DOUT + c0) = r;
}

// ---------------------------------------------------------------------------
// Layer-2 attention FUSED with partial mean-pool. 8 warps = 8 nodes/block;
// block partial (128 floats) to g_part.
// ---------------------------------------------------------------------------
__global__ void __launch_bounds__(256) attn2_pool_kernel(
    const float* __restrict__ xl, const float* __restrict__ xr,
    const float* __restrict__ att, const float* __restrict__ bias,
    float* __restrict__ part)
{
    constexpr int DOUT = D2, V = 4;
    __shared__ float sacc[8 * D2];

    int warp = threadIdx.x >> 5;
    int lane = threadIdx.x & 31;
    int node = blockIdx.x * 8 + warp;
    int b = node >> 10;
    const int* nidx = g_idx + (size_t)node * KK;
    int4 i0 = *(const int4*)nidx;
    int4 i1 = *(const int4*)(nidx + 4);
    int srcs[KK] = {i0.x, i0.y, i0.z, i0.w, i1.x, i1.y, i1.z, i1.w};

    int c0 = lane * V;

    float4 tr = *(const float4*)(xr + (size_t)node * DOUT + c0);
    float xrv[V] = {tr.x, tr.y, tr.z, tr.w};
    float4 ta = *(const float4*)(att + c0);
    float attv[V] = {ta.x, ta.y, ta.z, ta.w};

    float xnb[KK][V];
    float lg[KK];
#pragma unroll
    for (int k = 0; k < KK; k++) {
        int src = (b << 10) + srcs[k];
        float4 t = *(const float4*)(xl + (size_t)src * DOUT + c0);
        xnb[k][0] = t.x; xnb[k][1] = t.y; xnb[k][2] = t.z; xnb[k][3] = t.w;
        float s = 0.f;
#pragma unroll
        for (int v = 0; v < V; v++) {
            float e = xnb[k][v] + xrv[v];
            e = e > 0.f ? e : 0.2f * e;       // leaky_relu(0.2)
            s = fmaf(e, attv[v], s);
        }
        s += __shfl_xor_sync(0xffffffffu, s, 1);
        s += __shfl_xor_sync(0xffffffffu, s, 2);
        s += __shfl_xor_sync(0xffffffffu, s, 4);
        lg[k] = s;
    }

    float mx = lg[0];
#pragma unroll
    for (int k = 1; k < KK; k++) mx = fmaxf(mx, lg[k]);
    float ssum = 0.f;
#pragma unroll
    for (int k = 0; k < KK; k++) { lg[k] = __expf(lg[k] - mx); ssum += lg[k]; }
    float inv = 1.f / ssum;

    float o[V] = {0.f, 0.f, 0.f, 0.f};
#pragma unroll
    for (int k = 0; k < KK; k++) {
        float a = lg[k] * inv;
#pragma unroll
        for (int v = 0; v < V; v++) o[v] = fmaf(a, xnb[k][v], o[v]);
    }

    float4 bv = *(const float4*)(bias + c0);
    float4 r;
    r.x = fmaxf(o[0] + bv.x, 0.f);
    r.y = fmaxf(o[1] + bv.y, 0.f);
    r.z = fmaxf(o[2] + bv.z, 0.f);
    r.w = fmaxf(o[3] + bv.w, 0.f);
    *(float4*)(sacc + warp * D2 + c0) = r;
    __syncthreads();

    int t = threadIdx.x;
    if (t < D2) {
        float s = 0.f;
#pragma unroll
        for (int w = 0; w < 8; w++) s += sacc[w * D2 + t];
        part[(size_t)blockIdx.x * D2 + t] = s;
    }
}

// ---------------------------------------------------------------------------
// Final pool reduce: out[b][c] = (1/N) * sum over 128 block-partials.
// ---------------------------------------------------------------------------
__global__ void pool_reduce_kernel(const float* __restrict__ part,
                                   float* __restrict__ out)
{
    int b = blockIdx.x, t = threadIdx.x;  // 128 threads
    const float* p = part + (size_t)b * (NN / 8) * D2 + t;
    float s = 0.f;
#pragma unroll 8
    for (int j = 0; j < NN / 8; j++) s += p[(size_t)j * D2];
    out[b * D2 + t] = s * (1.f / (float)NN);
}

// ---------------------------------------------------------------------------
extern "C" void kernel_launch(void* const* d_in, const int* in_sizes, int n_in,
                              void* d_out, int out_size)
{
    const float* x     = (const float*)d_in[0];
    const float* pos   = (const float*)d_in[1];
    const float* Wl1   = (const float*)d_in[2];
    const float* bl1   = (const float*)d_in[3];
    const float* Wr1   = (const float*)d_in[4];
    const float* br1   = (const float*)d_in[5];
    const float* att1  = (const float*)d_in[6];
    const float* bias1 = (const float*)d_in[7];
    const float* Wl2   = (const float*)d_in[8];
    const float* bl2   = (const float*)d_in[9];
    const float* Wr2   = (const float*)d_in[10];
    const float* br2   = (const float*)d_in[11];
    const float* att2  = (const float*)d_in[12];
    const float* bias2 = (const float*)d_in[13];
    float* out = (float*)d_out;

    float *xl1, *xr1, *h1, *xl2, *xr2, *part;
    cudaGetSymbolAddress((void**)&xl1,  g_xl1);
    cudaGetSymbolAddress((void**)&xr1,  g_xr1);
    cudaGetSymbolAddress((void**)&h1,   g_h1);
    cudaGetSymbolAddress((void**)&xl2,  g_xl2);
    cudaGetSymbolAddress((void**)&xr2,  g_xr2);
    cudaGetSymbolAddress((void**)&part, g_part);

    // idx0-2: layer-1 transforms (Wl split in two so knn lands at idx3)
    gemm1_kernel<F1, D1><<<256, 256>>>(x, Wl1, bl1, xl1, 0);
    gemm1_kernel<F1, D1><<<256, 256>>>(x, Wl1, bl1, xl1, 32768);
    gemm1_kernel<F1, D1><<<512, 256>>>(x, Wr1, br1, xr1, 0);
    // idx3: KNN graph (PROFILED)
    knn_kernel<<<dim3(NN / 256, BB), 256>>>(pos);
    // idx4: layer-1 attention + ReLU
    attn1_kernel<<<(BB * NN * 32) / 256, 256>>>(xl1, xr1, att1, bias1, h1);
    // idx5: layer-2 transforms (combined grid.y picks Wl/Wr — R7 config)
    gemm2_kernel<D1, D2><<<dim3(BB * NN / 128, 2), 256>>>(
        h1, Wl2, bl2, Wr2, br2, xl2, xr2);
    // idx6: layer-2 attention + ReLU fused with partial mean pool
    attn2_pool_kernel<<<BB * NN / 8, 256>>>(xl2, xr2, att2, bias2, part);
    // idx7: final pool reduction
    pool_reduce_kernel<<<BB, 128>>>(part, out);
}